// round 16
// baseline (speedup 1.0000x reference)
#include <cuda_runtime.h>

// gconv_19301583028599 — adaptive graph conv as fused flash-attention.
// f32x2 v5: duplication moved into smem (V and Q stored dup) -> PV inner loop
// is pure LDS.128 + FFMA2 (no MOVs). NH=2 subtiles, 8 partial groups,
// deferred merge. FMA-pipe-bound by design.
//
// y = softmax(relu(adj @ adj^T)) @ X      (X = x transposed to [N, B*INP])
// out[b,n,o] = x[b,n,:]·W0[n,:,o] + y[b,n,:]·W1[n,:,o] + bias[n,o]

#define NN   8192
#define BB   32
#define EMB  16
#define TQ   64
#define KS   64          // keys per subtile
#define KITER 128        // keys per iteration (2 subtiles)

#define QTD_P 132        // dup Q pitch
#define PT_P  72
#define PT_SUB (KS * PT_P)      // 4608

// smem layout (float offsets)
#define OFF_QTD  0               // Qtd[d][dup 2r]     16 x 132 = 2112
#define OFF_KT   2112            // Kt[h][d][64]       2 x 16 x 64 = 2048
#define OFF_VSD  4160            // Vsd[h][k][128 dup,sw] 2 x 64 x 128 = 16384
#define OFF_PT   20544           // Pt[h][key][row 72] 2 x 64 x 72 = 9216 (ends 29760)
// overlays (after mainloop; Qtd at [0,2112) stays live for epilogue)
#define OFF_ACC2 2112            // 512 threads x 64 floats = 32768 (ends 34880)
#define OFF_YS   34880           // 64 x 68 = 4352 (ends 39232)
#define OFF_WPS  39232           // 4096 (ends 43328)
#define OFF_BPS  43328           // 1024 (ends 44352)
#define OFF_LRED 44352           // lred[half][64] = 128 — outside all overlays
#define SMEM_FLOATS 44480        // 177,920 B

typedef unsigned long long u64;

__device__ float g_Xt[NN * 64];   // Xt[m][2b+c] = x[b][m][c]

__global__ void transpose_x_kernel(const float* __restrict__ x) {
    int m = blockIdx.x * blockDim.x + threadIdx.x;
    if (m >= NN) return;
    float row[64];
#pragma unroll
    for (int b = 0; b < BB; b++) {
        float2 v = *(const float2*)(x + ((size_t)b * NN + m) * 2);
        row[2 * b] = v.x;  row[2 * b + 1] = v.y;
    }
    float4* dst = (float4*)(g_Xt + (size_t)m * 64);
#pragma unroll
    for (int q = 0; q < 16; q++) dst[q] = ((float4*)row)[q];
}

__device__ __forceinline__ u64 ffma2(u64 a, u64 b, u64 c) {
    u64 d;
    asm("fma.rn.f32x2 %0, %1, %2, %3;" : "=l"(d) : "l"(a), "l"(b), "l"(c));
    return d;
}
__device__ __forceinline__ u64 add2(u64 a, u64 b) {
    u64 d;
    asm("add.rn.f32x2 %0, %1, %2;" : "=l"(d) : "l"(a), "l"(b));
    return d;
}
__device__ __forceinline__ float2 unpk(u64 v) {
    float2 r;
    asm("mov.b64 {%0, %1}, %2;" : "=f"(r.x), "=f"(r.y) : "l"(v));
    return r;
}
__device__ __forceinline__ u64 pk2(float v) {   // (v, v)
    u64 d;
    asm("mov.b64 %0, {%1, %1};" : "=l"(d) : "f"(v));
    return d;
}

extern __shared__ float smf[];

__global__ __launch_bounds__(512, 1) void gconv_attn_kernel(
    const float* __restrict__ adj,
    const float* __restrict__ wp,
    const float* __restrict__ bp,
    float* __restrict__ out)
{
    float* Qtd  = smf + OFF_QTD;
    float* Kt   = smf + OFF_KT;
    float* Vsd  = smf + OFF_VSD;
    float* Pt   = smf + OFF_PT;
    float* lred = smf + OFF_LRED;

    const int tid  = threadIdx.x;
    // scores mapping: 2 subtiles x (16 row-groups x 16 key-groups)
    const int half = tid >> 8;          // 0..1 key-subtile
    const int t8   = tid & 255;
    const int i4   = t8 >> 4;           // 0..15: rows 4*i4..+3
    const int j4   = t8 & 15;           // 0..15: keys 4*j4..+3 (within subtile)
    // PV mapping: 8 partial groups x (8 row-groups x 8 col-groups)
    const int g    = tid >> 6;          // 0..7 partial group
    const int hh   = g >> 2;            // subtile
    const int g2   = g & 3;             // key phase
    const int i8   = (tid >> 3) & 7;    // rows 8*i8..+7
    const int j8   = tid & 7;           // cols 8*j8..+7
    const int n0   = blockIdx.x * TQ;

    // V-dup swizzled chunk offsets for cols 8j8..8j8+7 (chunks 4j8+qq)
    int offV[4];
#pragma unroll
    for (int qq = 0; qq < 4; qq++) {
        int c = 4 * j8 + qq;
        offV[qq] = 4 * (c ^ (c >> 2));
    }

    // stage Qtd (duplicated): Qtd[d][2r,2r+1] = adj[n0+r][d]
#pragma unroll
    for (int t = 0; t < 2; t++) {
        int idx = tid + 512 * t;
        int r = idx >> 4, d = idx & 15;
        float v = adj[(n0 + r) * EMB + d];
        *(float2*)&Qtd[d * QTD_P + 2 * r] = make_float2(v, v);
    }

    const float* ktp   = Kt + half * (EMB * 64) + 4 * j4;
    float*       ptw   = Pt + half * PT_SUB + 4 * i4;
    const float* qtp   = Qtd + 8 * i4;
    const float* pbase = Pt + hh * PT_SUB + 8 * i8;
    const float* vbase = Vsd + hh * 8192;

    u64 acc[4][8];
#pragma unroll
    for (int rp = 0; rp < 4; rp++)
#pragma unroll
        for (int c = 0; c < 8; c++) acc[rp][c] = 0;
    float l0 = 0.f, l1 = 0.f, l2 = 0.f, l3 = 0.f;

    const int sd = tid & 15, skr = tid >> 4;   // K staging ids

    for (int kt = 0; kt < NN; kt += KITER) {
        __syncthreads();   // prev PV done: Kt/Vsd safe to overwrite
        // ---- stage K (transposed): Kt[h][d][k] ----
#pragma unroll
        for (int m = 0; m < 4; m++) {
            int gk = skr + 32 * m;                 // iter key 0..127
            int h = gk >> 6, k = gk & 63;
            Kt[h * (EMB * 64) + sd * 64 + k] = adj[(kt + gk) * EMB + sd];
        }
        // ---- stage V DUPLICATED (chunk-swizzled): Vsd[h][k][2c..2c+1]=v_c ----
#pragma unroll
        for (int t = 0; t < 4; t++) {
            int idx = tid + 512 * t;               // 0..2047 float4 slots
            int row = idx >> 4, q = idx & 15;
            float4 v = *(const float4*)(g_Xt + (size_t)(kt + row) * 64 + 4 * q);
            float* base = Vsd + (row >> 6) * 8192 + (row & 63) * 128;
            int c0 = 2 * q, c1 = 2 * q + 1;
            *(ulonglong2*)(base + 4 * (c0 ^ (c0 >> 2))) =
                make_ulonglong2(pk2(v.x), pk2(v.y));
            *(ulonglong2*)(base + 4 * (c1 ^ (c1 >> 2))) =
                make_ulonglong2(pk2(v.z), pk2(v.w));
        }
        __syncthreads();

        // ---- scores: dup Q pairs x natural key pairs, zero MOVs ----
        u64 s[8];
#pragma unroll
        for (int t = 0; t < 8; t++) s[t] = 0;
#pragma unroll
        for (int d = 0; d < EMB; d++) {
            const float* qd_ = qtp + d * QTD_P;
            ulonglong2 qA = *(const ulonglong2*)(qd_);       // dup(r0), dup(r1)
            ulonglong2 qB = *(const ulonglong2*)(qd_ + 4);   // dup(r2), dup(r3)
            ulonglong2 kA = *(const ulonglong2*)(ktp + d * 64); // key pairs (0,1),(2,3)
            s[0] = ffma2(qA.x, kA.x, s[0]);  s[1] = ffma2(qA.x, kA.y, s[1]);
            s[2] = ffma2(qA.y, kA.x, s[2]);  s[3] = ffma2(qA.y, kA.y, s[3]);
            s[4] = ffma2(qB.x, kA.x, s[4]);  s[5] = ffma2(qB.x, kA.y, s[5]);
            s[6] = ffma2(qB.y, kA.x, s[6]);  s[7] = ffma2(qB.y, kA.y, s[7]);
        }
        // ---- p = exp(relu(s)) = max(exp(s),1); row sums; P store ----
        float pr[4][4];
#pragma unroll
        for (int r = 0; r < 4; r++) {
            float2 ua = unpk(s[2 * r]);       // keys 4j4, 4j4+1
            float2 ub = unpk(s[2 * r + 1]);   // keys 4j4+2, 4j4+3
            pr[r][0] = fmaxf(__expf(ua.x), 1.0f);
            pr[r][1] = fmaxf(__expf(ua.y), 1.0f);
            pr[r][2] = fmaxf(__expf(ub.x), 1.0f);
            pr[r][3] = fmaxf(__expf(ub.y), 1.0f);
        }
#pragma unroll
        for (int c = 0; c < 4; c++) {
            l0 += pr[0][c]; l1 += pr[1][c]; l2 += pr[2][c]; l3 += pr[3][c];
            *(float4*)(ptw + (4 * j4 + c) * PT_P) =
                make_float4(pr[0][c], pr[1][c], pr[2][c], pr[3][c]);
        }
        __syncthreads();   // P ready

        // ---- PV: pure 6 LDS.128 + 32 FFMA2 per key ----
#pragma unroll 4
        for (int kk = 0; kk < 16; kk++) {
            int key = g2 + 4 * kk;
            const float* pk_ = pbase + key * PT_P;
            ulonglong2 pp0 = *(const ulonglong2*)pk_;          // row pairs (0,1),(2,3)
            ulonglong2 pp1 = *(const ulonglong2*)(pk_ + 4);    // row pairs (4,5),(6,7)
            const float* vk = vbase + key * 128;
            ulonglong2 vA = *(const ulonglong2*)(vk + offV[0]); // dup cols 8j8, +1
            ulonglong2 vB = *(const ulonglong2*)(vk + offV[1]); // +2, +3
            ulonglong2 vC = *(const ulonglong2*)(vk + offV[2]); // +4, +5
            ulonglong2 vD = *(const ulonglong2*)(vk + offV[3]); // +6, +7
            u64 p0 = pp0.x, p1 = pp0.y, p2 = pp1.x, p3 = pp1.y;
            acc[0][0] = ffma2(p0, vA.x, acc[0][0]); acc[0][1] = ffma2(p0, vA.y, acc[0][1]);
            acc[0][2] = ffma2(p0, vB.x, acc[0][2]); acc[0][3] = ffma2(p0, vB.y, acc[0][3]);
            acc[0][4] = ffma2(p0, vC.x, acc[0][4]); acc[0][5] = ffma2(p0, vC.y, acc[0][5]);
            acc[0][6] = ffma2(p0, vD.x, acc[0][6]); acc[0][7] = ffma2(p0, vD.y, acc[0][7]);
            acc[1][0] = ffma2(p1, vA.x, acc[1][0]); acc[1][1] = ffma2(p1, vA.y, acc[1][1]);
            acc[1][2] = ffma2(p1, vB.x, acc[1][2]); acc[1][3] = ffma2(p1, vB.y, acc[1][3]);
            acc[1][4] = ffma2(p1, vC.x, acc[1][4]); acc[1][5] = ffma2(p1, vC.y, acc[1][5]);
            acc[1][6] = ffma2(p1, vD.x, acc[1][6]); acc[1][7] = ffma2(p1, vD.y, acc[1][7]);
            acc[2][0] = ffma2(p2, vA.x, acc[2][0]); acc[2][1] = ffma2(p2, vA.y, acc[2][1]);
            acc[2][2] = ffma2(p2, vB.x, acc[2][2]); acc[2][3] = ffma2(p2, vB.y, acc[2][3]);
            acc[2][4] = ffma2(p2, vC.x, acc[2][4]); acc[2][5] = ffma2(p2, vC.y, acc[2][5]);
            acc[2][6] = ffma2(p2, vD.x, acc[2][6]); acc[2][7] = ffma2(p2, vD.y, acc[2][7]);
            acc[3][0] = ffma2(p3, vA.x, acc[3][0]); acc[3][1] = ffma2(p3, vA.y, acc[3][1]);
            acc[3][2] = ffma2(p3, vB.x, acc[3][2]); acc[3][3] = ffma2(p3, vB.y, acc[3][3]);
            acc[3][4] = ffma2(p3, vC.x, acc[3][4]); acc[3][5] = ffma2(p3, vC.y, acc[3][5]);
            acc[3][6] = ffma2(p3, vD.x, acc[3][6]); acc[3][7] = ffma2(p3, vD.y, acc[3][7]);
        }
    }
    __syncthreads();   // S1: all PV reads done

    // ---- row-sum reduce over j4 (lane bits 0..3) ----
    l0 += __shfl_xor_sync(0xffffffffu, l0, 1);
    l0 += __shfl_xor_sync(0xffffffffu, l0, 2);
    l0 += __shfl_xor_sync(0xffffffffu, l0, 4);
    l0 += __shfl_xor_sync(0xffffffffu, l0, 8);
    l1 += __shfl_xor_sync(0xffffffffu, l1, 1);
    l1 += __shfl_xor_sync(0xffffffffu, l1, 2);
    l1 += __shfl_xor_sync(0xffffffffu, l1, 4);
    l1 += __shfl_xor_sync(0xffffffffu, l1, 8);
    l2 += __shfl_xor_sync(0xffffffffu, l2, 1);
    l2 += __shfl_xor_sync(0xffffffffu, l2, 2);
    l2 += __shfl_xor_sync(0xffffffffu, l2, 4);
    l2 += __shfl_xor_sync(0xffffffffu, l2, 8);
    l3 += __shfl_xor_sync(0xffffffffu, l3, 1);
    l3 += __shfl_xor_sync(0xffffffffu, l3, 2);
    l3 += __shfl_xor_sync(0xffffffffu, l3, 4);
    l3 += __shfl_xor_sync(0xffffffffu, l3, 8);
    if ((tid & 15) == 0)
        *(float4*)&lred[half * 64 + 4 * i4] = make_float4(l0, l1, l2, l3);

    // ---- stage all 8 partial-accumulator groups (overlay; Qtd preserved) ----
    {
        float* st = smf + OFF_ACC2 + (size_t)tid * 64;   // [rp][c] at rp*16 + 2c
#pragma unroll
        for (int rp = 0; rp < 4; rp++)
#pragma unroll
            for (int c = 0; c < 8; c += 2) {
                *(u64*)(st + rp * 16 + 2 * c)     = acc[rp][c];
                *(u64*)(st + rp * 16 + 2 * c + 2) = acc[rp][c + 1];
            }
    }
    // stage pools
    float* wpsm = smf + OFF_WPS;
    float* bpsm = smf + OFF_BPS;
    ((float4*)wpsm)[tid]       = ((const float4*)wp)[tid];
    ((float4*)wpsm)[tid + 512] = ((const float4*)wp)[tid + 512];
    if (tid < 256) ((float4*)bpsm)[tid] = ((const float4*)bp)[tid];
    __syncthreads();   // S2

    // ---- merge 8 partials, normalize, write Ysm ----
    float* Ysm = smf + OFF_YS;
    {
        const int u0 = 4 * tid;              // u64 ids (2048 total: 32 row-pairs x 64 cols)
        const int RP = u0 >> 6;              // row-pair 0..31
        const int c0 = u0 & 63;
        const int r0 = 2 * RP;
        float La = lred[r0]     + lred[64 + r0];
        float Lb = lred[r0 + 1] + lred[64 + r0 + 1];
        float inv0 = 1.f / La, inv1 = 1.f / Lb;
        const int i8m = RP >> 2, rpm = RP & 3;
#pragma unroll
        for (int m4 = 0; m4 < 4; m4++) {
            int c = c0 + m4;
            int j8m = c >> 3, cm = c & 7;
            const float* base = smf + OFF_ACC2 +
                (size_t)((i8m * 8 + j8m) * 64 + rpm * 16 + 2 * cm);
            u64 sum = *(const u64*)base;
#pragma unroll
            for (int h = 1; h < 8; h++)
                sum = add2(sum, *(const u64*)(base + (size_t)h * 4096));
            float2 yv = unpk(sum);
            Ysm[r0 * 68 + c]       = yv.x * inv0;
            Ysm[(r0 + 1) * 68 + c] = yv.y * inv1;
        }
    }
    __syncthreads();   // S3

    // ---- epilogue: out[b,n,o] = bias + x·W0 + y·W1 ----
    const int o  = tid & 63;
    const int ng = tid >> 6;   // 0..7, 8 rows each
#pragma unroll
    for (int q = 0; q < 8; q++) {
        int n = ng * 8 + q;
        float w00 = 0.f, w01 = 0.f, w10 = 0.f, w11 = 0.f, bbv = 0.f;
#pragma unroll
        for (int d = 0; d < EMB; d++) {
            float a = Qtd[d * QTD_P + 2 * n];
            const float* wrow = wpsm + d * 256 + o;   // (d*4 + 2k + i)*64 + o
            w00 += a * wrow[0];
            w01 += a * wrow[64];
            w10 += a * wrow[128];
            w11 += a * wrow[192];
            bbv += a * bpsm[d * 64 + o];
        }
        int gn = n0 + n;
        const float* xrow = g_Xt + (size_t)gn * 64;
        const float* yrow = Ysm + n * 68;
        float* orow = out + (size_t)gn * 64 + o;
#pragma unroll 4
        for (int b = 0; b < BB; b++) {
            float2 xv = *(const float2*)(xrow + 2 * b);
            float2 yv = *(const float2*)(yrow + 2 * b);
            orow[(size_t)b * (NN * 64)] = bbv + xv.x * w00 + xv.y * w01 + yv.x * w10 + yv.y * w11;
        }
    }
}

extern "C" void kernel_launch(void* const* d_in, const int* in_sizes, int n_in,
                              void* d_out, int out_size) {
    const float* x   = (const float*)d_in[0];   // [32, 8192, 2]
    const float* adj = (const float*)d_in[1];   // [8192, 16]
    const float* wp  = (const float*)d_in[2];   // [16, 2, 2, 64]
    const float* bp  = (const float*)d_in[3];   // [16, 64]
    float* out = (float*)d_out;                 // [32, 8192, 64]

    cudaFuncSetAttribute(gconv_attn_kernel,
                         cudaFuncAttributeMaxDynamicSharedMemorySize,
                         SMEM_FLOATS * (int)sizeof(float));
    transpose_x_kernel<<<NN / 256, 256>>>(x);
    gconv_attn_kernel<<<NN / TQ, 512, SMEM_FLOATS * sizeof(float)>>>(adj, wp, bp, out);
}

// round 17
// speedup vs baseline: 1.4369x; 1.4369x over previous
#include <cuda_runtime.h>

// gconv_19301583028599 — adaptive graph conv as fused flash-attention.
// f32x2 v6: v4b compute structure + double-buffered K/V (NH=2) so staging
// LDGs overlap scores/exp; 2 barriers/iter; conflict-free P load path via
// chunk swizzle; dup-Q in smem. Crossbar kept minimal (v5 lesson).
//
// y = softmax(relu(adj @ adj^T)) @ X      (X = x transposed to [N, B*INP])
// out[b,n,o] = x[b,n,:]·W0[n,:,o] + y[b,n,:]·W1[n,:,o] + bias[n,o]

#define NN   8192
#define BB   32
#define EMB  16
#define TQ   64
#define KITER 128        // keys per iteration (2 subtiles of 64)

#define QTD_P 132
#define PT_P  68
#define PT_SUB (64 * PT_P)       // 4352

// smem layout (float offsets)
#define OFF_QTD  0               // Qtd[d][dup 2r]        16 x 132 = 2112
#define OFF_KT   2112            // Kt[buf][h][d][64sw+4] 2 x 2 x 16 x 68 = 4352 (ends 6464)
#define OFF_VS   6464            // Vs[buf][h][k][64 sw]  2 x 2 x 64 x 64 = 16384 (ends 22848)
#define OFF_PT   22848           // Pt[h][rho][68]        2 x 64 x 68 = 8704 (ends 31552)
// overlays (after mainloop; Qtd stays live for epilogue)
#define OFF_ACC2 2112            // 512 threads x 64 = 32768 (ends 34880)
#define OFF_YS   34880           // 64 x 68 = 4352 (ends 39232)
#define OFF_WPS  39232           // 4096 (ends 43328)
#define OFF_BPS  43328           // 1024 (ends 44352)
#define OFF_LRED 44352           // lred[half][64] = 128 — outside all overlays
#define SMEM_FLOATS 44480        // 177,920 B

typedef unsigned long long u64;

__device__ float g_Xt[NN * 64];   // Xt[m][2b+c] = x[b][m][c]

__global__ void transpose_x_kernel(const float* __restrict__ x) {
    int m = blockIdx.x * blockDim.x + threadIdx.x;
    if (m >= NN) return;
    float row[64];
#pragma unroll
    for (int b = 0; b < BB; b++) {
        float2 v = *(const float2*)(x + ((size_t)b * NN + m) * 2);
        row[2 * b] = v.x;  row[2 * b + 1] = v.y;
    }
    float4* dst = (float4*)(g_Xt + (size_t)m * 64);
#pragma unroll
    for (int q = 0; q < 16; q++) dst[q] = ((float4*)row)[q];
}

__device__ __forceinline__ u64 ffma2(u64 a, u64 b, u64 c) {
    u64 d;
    asm("fma.rn.f32x2 %0, %1, %2, %3;" : "=l"(d) : "l"(a), "l"(b), "l"(c));
    return d;
}
__device__ __forceinline__ u64 add2(u64 a, u64 b) {
    u64 d;
    asm("add.rn.f32x2 %0, %1, %2;" : "=l"(d) : "l"(a), "l"(b));
    return d;
}
__device__ __forceinline__ float2 unpk(u64 v) {
    float2 r;
    asm("mov.b64 {%0, %1}, %2;" : "=f"(r.x), "=f"(r.y) : "l"(v));
    return r;
}
__device__ __forceinline__ u64 pk2(float v) {   // (v, v)
    u64 d;
    asm("mov.b64 %0, {%1, %1};" : "=l"(d) : "f"(v));
    return d;
}

extern __shared__ float smf[];

__global__ __launch_bounds__(512, 1) void gconv_attn_kernel(
    const float* __restrict__ adj,
    const float* __restrict__ wp,
    const float* __restrict__ bp,
    float* __restrict__ out)
{
    float* Qtd  = smf + OFF_QTD;
    float* Kt   = smf + OFF_KT;
    float* Vs   = smf + OFF_VS;
    float* Pt   = smf + OFF_PT;
    float* lred = smf + OFF_LRED;

    const int tid  = threadIdx.x;
    // scores mapping: 2 subtiles x (16 row-groups x 16 key-groups)
    const int half = tid >> 8;          // 0..1 key-subtile
    const int t8   = tid & 255;
    const int i4   = t8 >> 4;           // rows 4*i4..+3
    const int j4   = t8 & 15;           // keys 4*j4..+3 (within subtile)
    // PV mapping: 8 partial groups (2 subtiles x 4 key phases)
    const int g    = tid >> 6;          // 0..7
    const int hh   = g >> 2;            // subtile
    const int g2   = g & 3;             // key phase (key % 4)
    const int i8   = (tid >> 3) & 7;    // rows 8*i8..+7
    const int j8   = tid & 7;           // cols 8*j8..+7
    const int n0   = blockIdx.x * TQ;

    // swizzled offsets
    const int offK  = 4 * (j4 ^ (j4 >> 3));                       // K quad j4
    const int qa = 2 * j8, qb = 2 * j8 + 1;
    const int offA = 4 * (qa ^ (qa >> 3));                        // V quads
    const int offB = 4 * (qb ^ (qb >> 3));
    const int pst  = 4 * (i4 ^ (i4 >> 3));                        // P store chunk i4
    const int c0v = 2 * i8, c1v = 2 * i8 + 1;
    const int offP0 = 4 * (c0v ^ (c0v >> 3));                     // P load chunks
    const int offP1 = 4 * (c1v ^ (c1v >> 3));

    // stage Qtd (duplicated): Qtd[d][2r,2r+1] = adj[n0+r][d]
#pragma unroll
    for (int t = 0; t < 2; t++) {
        int idx = tid + 512 * t;
        int r = idx >> 4, d = idx & 15;
        float v = adj[(n0 + r) * EMB + d];
        *(float2*)&Qtd[d * QTD_P + 2 * r] = make_float2(v, v);
    }

    const float* qtp = Qtd + 8 * i4;
    float*       ptw = Pt + half * PT_SUB;
    const float* pb  = Pt + hh * PT_SUB;

    u64 acc[4][8];
#pragma unroll
    for (int rp = 0; rp < 4; rp++)
#pragma unroll
        for (int c = 0; c < 8; c++) acc[rp][c] = 0;
    float l0 = 0.f, l1 = 0.f, l2 = 0.f, l3 = 0.f;

    const int sd = tid & 15, skr = tid >> 4;   // staging ids

    // ---- pre-stage tile 0 into buf 0 ----
#pragma unroll
    for (int m = 0; m < 4; m++) {
        int gk = skr + 32 * m;                 // key 0..127
        int h = gk >> 6, k = gk & 63;
        int q = k >> 2, p = k & 3;
        Kt[h * 1088 + sd * 68 + 4 * (q ^ (q >> 3)) + p] = adj[gk * EMB + sd];
    }
#pragma unroll
    for (int t = 0; t < 4; t++) {
        int idx = tid + 512 * t;               // 0..2047 float4 slots
        int row = idx >> 4, q = idx & 15;
        float4 v = *(const float4*)(g_Xt + (size_t)row * 64 + 4 * q);
        *(float4*)&Vs[(row >> 6) * 4096 + (row & 63) * 64 + 4 * (q ^ (q >> 3))] = v;
    }

    int buf = 0;
    for (int kt = 0; kt < NN; kt += KITER, buf ^= 1) {
        __syncthreads();   // S_a: PV(i-1)+staging(i-1) done; buf data ready

        // ---- LDG next tile (drains under scores/exp) ----
        int ktn = kt + KITER; if (ktn >= NN) ktn = 0;
        float  kpf[4];
        float4 vpf[4];
#pragma unroll
        for (int m = 0; m < 4; m++)
            kpf[m] = adj[(ktn + skr + 32 * m) * EMB + sd];
#pragma unroll
        for (int t = 0; t < 4; t++) {
            int idx = tid + 512 * t;
            vpf[t] = *(const float4*)(g_Xt + (size_t)(ktn + (idx >> 4)) * 64 + 4 * (idx & 15));
        }

        // ---- scores: dup-Q pairs x key pairs (no MOVs) ----
        const float* kb = Kt + buf * 2176 + half * 1088 + offK;
        u64 s[8];
#pragma unroll
        for (int t = 0; t < 8; t++) s[t] = 0;
#pragma unroll
        for (int d = 0; d < EMB; d++) {
            const float* qd_ = qtp + d * QTD_P;
            ulonglong2 qA = *(const ulonglong2*)(qd_);       // dup(r0), dup(r1)
            ulonglong2 qB = *(const ulonglong2*)(qd_ + 4);   // dup(r2), dup(r3)
            ulonglong2 kA = *(const ulonglong2*)(kb + d * 68); // key pairs (0,1),(2,3)
            s[0] = ffma2(qA.x, kA.x, s[0]);  s[1] = ffma2(qA.x, kA.y, s[1]);
            s[2] = ffma2(qA.y, kA.x, s[2]);  s[3] = ffma2(qA.y, kA.y, s[3]);
            s[4] = ffma2(qB.x, kA.x, s[4]);  s[5] = ffma2(qB.x, kA.y, s[5]);
            s[6] = ffma2(qB.y, kA.x, s[6]);  s[7] = ffma2(qB.y, kA.y, s[7]);
        }
        // ---- p = exp(relu(s)) = max(exp(s),1); row sums; swizzled P store ----
        float pr[4][4];
#pragma unroll
        for (int r = 0; r < 4; r++) {
            float2 ua = unpk(s[2 * r]);       // keys 4j4, 4j4+1
            float2 ub = unpk(s[2 * r + 1]);   // keys 4j4+2, 4j4+3
            pr[r][0] = fmaxf(__expf(ua.x), 1.0f);
            pr[r][1] = fmaxf(__expf(ua.y), 1.0f);
            pr[r][2] = fmaxf(__expf(ub.x), 1.0f);
            pr[r][3] = fmaxf(__expf(ub.y), 1.0f);
        }
#pragma unroll
        for (int c = 0; c < 4; c++) {
            l0 += pr[0][c]; l1 += pr[1][c]; l2 += pr[2][c]; l3 += pr[3][c];
            // key k = 4*j4 + c  ->  rho = 16*c + j4 ; row-chunk i4 at swizzled pos
            *(float4*)(ptw + (16 * c + j4) * PT_P + pst) =
                make_float4(pr[0][c], pr[1][c], pr[2][c], pr[3][c]);
        }

        // ---- STS next tile into other buffer ----
#pragma unroll
        for (int m = 0; m < 4; m++) {
            int gk = skr + 32 * m;
            int h = gk >> 6, k = gk & 63;
            int q = k >> 2, p = k & 3;
            Kt[(buf ^ 1) * 2176 + h * 1088 + sd * 68 + 4 * (q ^ (q >> 3)) + p] = kpf[m];
        }
#pragma unroll
        for (int t = 0; t < 4; t++) {
            int idx = tid + 512 * t;
            int row = idx >> 4, q = idx & 15;
            *(float4*)&Vs[(buf ^ 1) * 8192 + (row >> 6) * 4096 + (row & 63) * 64 +
                          4 * (q ^ (q >> 3))] = vpf[t];
        }
        __syncthreads();   // S_c: P ready

        // ---- PV: 16 keys (phase g2), 4 LDS.128 + 32 FFMA2 per key ----
        const float* vb = Vs + buf * 8192 + hh * 4096;
#pragma unroll 4
        for (int j = 0; j < 16; j++) {
            const float* pk_ = pb + (16 * g2 + j) * PT_P;
            ulonglong2 pp0 = *(const ulonglong2*)(pk_ + offP0);  // rows 8i8..+3
            ulonglong2 pp1 = *(const ulonglong2*)(pk_ + offP1);  // rows 8i8+4..+7
            const float* vk = vb + (4 * j + g2) * 64;
            ulonglong2 vA = *(const ulonglong2*)(vk + offA);     // cols 8j8..+3
            ulonglong2 vB = *(const ulonglong2*)(vk + offB);     // cols 8j8+4..+7
            float2 fa = unpk(vA.x), fb = unpk(vA.y), fc = unpk(vB.x), fd = unpk(vB.y);
            u64 d0 = pk2(fa.x), d1 = pk2(fa.y), d2 = pk2(fb.x), d3 = pk2(fb.y);
            u64 d4 = pk2(fc.x), d5 = pk2(fc.y), d6 = pk2(fd.x), d7 = pk2(fd.y);
            u64 p0 = pp0.x, p1 = pp0.y, p2 = pp1.x, p3 = pp1.y;
            acc[0][0] = ffma2(p0, d0, acc[0][0]); acc[0][1] = ffma2(p0, d1, acc[0][1]);
            acc[0][2] = ffma2(p0, d2, acc[0][2]); acc[0][3] = ffma2(p0, d3, acc[0][3]);
            acc[0][4] = ffma2(p0, d4, acc[0][4]); acc[0][5] = ffma2(p0, d5, acc[0][5]);
            acc[0][6] = ffma2(p0, d6, acc[0][6]); acc[0][7] = ffma2(p0, d7, acc[0][7]);
            acc[1][0] = ffma2(p1, d0, acc[1][0]); acc[1][1] = ffma2(p1, d1, acc[1][1]);
            acc[1][2] = ffma2(p1, d2, acc[1][2]); acc[1][3] = ffma2(p1, d3, acc[1][3]);
            acc[1][4] = ffma2(p1, d4, acc[1][4]); acc[1][5] = ffma2(p1, d5, acc[1][5]);
            acc[1][6] = ffma2(p1, d6, acc[1][6]); acc[1][7] = ffma2(p1, d7, acc[1][7]);
            acc[2][0] = ffma2(p2, d0, acc[2][0]); acc[2][1] = ffma2(p2, d1, acc[2][1]);
            acc[2][2] = ffma2(p2, d2, acc[2][2]); acc[2][3] = ffma2(p2, d3, acc[2][3]);
            acc[2][4] = ffma2(p2, d4, acc[2][4]); acc[2][5] = ffma2(p2, d5, acc[2][5]);
            acc[2][6] = ffma2(p2, d6, acc[2][6]); acc[2][7] = ffma2(p2, d7, acc[2][7]);
            acc[3][0] = ffma2(p3, d0, acc[3][0]); acc[3][1] = ffma2(p3, d1, acc[3][1]);
            acc[3][2] = ffma2(p3, d2, acc[3][2]); acc[3][3] = ffma2(p3, d3, acc[3][3]);
            acc[3][4] = ffma2(p3, d4, acc[3][4]); acc[3][5] = ffma2(p3, d5, acc[3][5]);
            acc[3][6] = ffma2(p3, d6, acc[3][6]); acc[3][7] = ffma2(p3, d7, acc[3][7]);
        }
    }
    __syncthreads();   // S1: all PV reads done

    // ---- row-sum reduce over j4 (lane bits 0..3) ----
    l0 += __shfl_xor_sync(0xffffffffu, l0, 1);
    l0 += __shfl_xor_sync(0xffffffffu, l0, 2);
    l0 += __shfl_xor_sync(0xffffffffu, l0, 4);
    l0 += __shfl_xor_sync(0xffffffffu, l0, 8);
    l1 += __shfl_xor_sync(0xffffffffu, l1, 1);
    l1 += __shfl_xor_sync(0xffffffffu, l1, 2);
    l1 += __shfl_xor_sync(0xffffffffu, l1, 4);
    l1 += __shfl_xor_sync(0xffffffffu, l1, 8);
    l2 += __shfl_xor_sync(0xffffffffu, l2, 1);
    l2 += __shfl_xor_sync(0xffffffffu, l2, 2);
    l2 += __shfl_xor_sync(0xffffffffu, l2, 4);
    l2 += __shfl_xor_sync(0xffffffffu, l2, 8);
    l3 += __shfl_xor_sync(0xffffffffu, l3, 1);
    l3 += __shfl_xor_sync(0xffffffffu, l3, 2);
    l3 += __shfl_xor_sync(0xffffffffu, l3, 4);
    l3 += __shfl_xor_sync(0xffffffffu, l3, 8);
    if ((tid & 15) == 0)
        *(float4*)&lred[half * 64 + 4 * i4] = make_float4(l0, l1, l2, l3);

    // ---- stage all 8 partial-accumulator groups (overlay; Qtd preserved) ----
    {
        float* st = smf + OFF_ACC2 + (size_t)tid * 64;   // [rp][c] at rp*16 + 2c
#pragma unroll
        for (int rp = 0; rp < 4; rp++)
#pragma unroll
            for (int c = 0; c < 8; c += 2) {
                *(u64*)(st + rp * 16 + 2 * c)     = acc[rp][c];
                *(u64*)(st + rp * 16 + 2 * c + 2) = acc[rp][c + 1];
            }
    }
    // stage pools
    float* wpsm = smf + OFF_WPS;
    float* bpsm = smf + OFF_BPS;
    ((float4*)wpsm)[tid]       = ((const float4*)wp)[tid];
    ((float4*)wpsm)[tid + 512] = ((const float4*)wp)[tid + 512];
    if (tid < 256) ((float4*)bpsm)[tid] = ((const float4*)bp)[tid];
    __syncthreads();   // S2

    // ---- merge 8 partials, normalize, write Ysm ----
    float* Ysm = smf + OFF_YS;
    {
        const int u0 = 4 * tid;              // u64 ids (2048: 32 row-pairs x 64 cols)
        const int RP = u0 >> 6;              // row-pair 0..31
        const int c0 = u0 & 63;
        const int r0 = 2 * RP;
        float La = lred[r0]     + lred[64 + r0];
        float Lb = lred[r0 + 1] + lred[64 + r0 + 1];
        float inv0 = 1.f / La, inv1 = 1.f / Lb;
        const int i8m = RP >> 2, rpm = RP & 3;
#pragma unroll
        for (int m4 = 0; m4 < 4; m4++) {
            int c = c0 + m4;
            int j8m = c >> 3, cm = c & 7;
            const float* base = smf + OFF_ACC2 +
                (size_t)((i8m * 8 + j8m) * 64 + rpm * 16 + 2 * cm);
            u64 sum = *(const u64*)base;
#pragma unroll
            for (int h = 1; h < 8; h++)
                sum = add2(sum, *(const u64*)(base + (size_t)h * 4096));
            float2 yv = unpk(sum);
            Ysm[r0 * 68 + c]       = yv.x * inv0;
            Ysm[(r0 + 1) * 68 + c] = yv.y * inv1;
        }
    }
    __syncthreads();   // S3

    // ---- epilogue: out[b,n,o] = bias + x·W0 + y·W1 ----
    const int o  = tid & 63;
    const int ng = tid >> 6;   // 0..7, 8 rows each
#pragma unroll
    for (int q = 0; q < 8; q++) {
        int n = ng * 8 + q;
        float w00 = 0.f, w01 = 0.f, w10 = 0.f, w11 = 0.f, bbv = 0.f;
#pragma unroll
        for (int d = 0; d < EMB; d++) {
            float a = Qtd[d * QTD_P + 2 * n];
            const float* wrow = wpsm + d * 256 + o;   // (d*4 + 2k + i)*64 + o
            w00 += a * wrow[0];
            w01 += a * wrow[64];
            w10 += a * wrow[128];
            w11 += a * wrow[192];
            bbv += a * bpsm[d * 64 + o];
        }
        int gn = n0 + n;
        const float* xrow = g_Xt + (size_t)gn * 64;
        const float* yrow = Ysm + n * 68;
        float* orow = out + (size_t)gn * 64 + o;
#pragma unroll 4
        for (int b = 0; b < BB; b++) {
            float2 xv = *(const float2*)(xrow + 2 * b);
            float2 yv = *(const float2*)(yrow + 2 * b);
            orow[(size_t)b * (NN * 64)] = bbv + xv.x * w00 + xv.y * w01 + yv.x * w10 + yv.y * w11;
        }
    }
}

extern "C" void kernel_launch(void* const* d_in, const int* in_sizes, int n_in,
                              void* d_out, int out_size) {
    const float* x   = (const float*)d_in[0];   // [32, 8192, 2]
    const float* adj = (const float*)d_in[1];   // [8192, 16]
    const float* wp  = (const float*)d_in[2];   // [16, 2, 2, 64]
    const float* bp  = (const float*)d_in[3];   // [16, 64]
    float* out = (float*)d_out;                 // [32, 8192, 64]

    cudaFuncSetAttribute(gconv_attn_kernel,
                         cudaFuncAttributeMaxDynamicSharedMemorySize,
                         SMEM_FLOATS * (int)sizeof(float));
    transpose_x_kernel<<<NN / 256, 256>>>(x);
    gconv_attn_kernel<<<NN / TQ, 512, SMEM_FLOATS * sizeof(float)>>>(adj, wp, bp, out);
}